// round 3
// baseline (speedup 1.0000x reference)
#include <cuda_runtime.h>
#include <math.h>
#include <mma.h>

using namespace nvcuda;

#define NTOT   50000
#define NTYPE0 30000
#define ETOT   400000
#define NPAD   50048

// ---------------- static scratch ----------------
__device__ float g_h[NPAD * 256];
__device__ float g_acc[NPAD * 256];
__device__ float g_feat[2 * NPAD * 256];
__device__ float g_l2out[NPAD * 64];
__device__ float g_w2pack[256 * 64];
__device__ float g_el[2][NTOT * 4];
__device__ float g_er[2][NTOT * 4];
__device__ float g_alpha[2][ETOT * 4];
__device__ int   g_rowptr[2][NTOT + 1];
__device__ int   g_cursor[2][NTOT];
__device__ int   g_counts[2][NTOT];
__device__ int   g_csrsrc[2][ETOT];

__device__ __forceinline__ float f2tf32(float v) {
    unsigned u;
    asm("cvt.rna.tf32.f32 %0, %1;" : "=r"(u) : "f"(v));
    return __uint_as_float(u);
}

// ---------------- CSR build ----------------
__global__ void count_k(const int* __restrict__ dst, int* __restrict__ counts)
{
    int e = blockIdx.x * blockDim.x + threadIdx.x;
    if (e < ETOT) atomicAdd(&counts[dst[e]], 1);
}

__global__ void scan_k(const int* __restrict__ counts, int* __restrict__ rowptr,
                       int* __restrict__ cursor)
{
    __shared__ int warp_sums[32];
    __shared__ int s_carry;
    int tid = threadIdx.x, lane = tid & 31, wid = tid >> 5;
    int nw = blockDim.x >> 5;
    if (tid == 0) s_carry = 0;
    __syncthreads();
    for (int base = 0; base < NTOT; base += blockDim.x) {
        int i = base + tid;
        int v = (i < NTOT) ? counts[i] : 0;
        int x = v;
#pragma unroll
        for (int o = 1; o < 32; o <<= 1) {
            int y = __shfl_up_sync(~0u, x, o);
            if (lane >= o) x += y;
        }
        if (lane == 31) warp_sums[wid] = x;
        __syncthreads();
        if (wid == 0) {
            int s = (lane < nw) ? warp_sums[lane] : 0;
#pragma unroll
            for (int o = 1; o < 32; o <<= 1) {
                int y = __shfl_up_sync(~0u, s, o);
                if (lane >= o) s += y;
            }
            warp_sums[lane] = s;
        }
        __syncthreads();
        int woff = (wid == 0) ? 0 : warp_sums[wid - 1];
        int incl = x + woff;
        int excl = incl - v;
        int carry = s_carry;
        if (i < NTOT) { rowptr[i] = carry + excl; cursor[i] = carry + excl; }
        __syncthreads();
        if (tid == blockDim.x - 1) s_carry = carry + incl;
        __syncthreads();
    }
    if (tid == 0) rowptr[NTOT] = s_carry;
}

__global__ void scatter_k(const int* __restrict__ src, const int* __restrict__ dst,
                          int* __restrict__ cursor, int* __restrict__ csrsrc)
{
    int e = blockIdx.x * blockDim.x + threadIdx.x;
    if (e >= ETOT) return;
    int pos = atomicAdd(&cursor[dst[e]], 1);
    csrsrc[pos] = src[e];
}

// ---------------- 3xTF32 tensor-core GEMM ----------------
// BM=128, BK=16, 256 threads (8 warps as 4x2), warp tile 32 x (BN/2).
// Stores are unguarded: C buffers are padded to a multiple of 128 rows (or have slack).
// A loads are guarded by M; out-of-range rows contribute zeros.
template<int BN>
__global__ void __launch_bounds__(256)
gemm_tf32(const float* __restrict__ A, const float* __restrict__ B,
          float* __restrict__ C, int M, int K, int N,
          long long bStride, long long cStride)
{
    constexpr int BM = 128, BK = 16;
    constexpr int BKP = BK + 4;
    constexpr int BNP = BN + 4;
    constexpr int WN = BN / 2;
    constexpr int CF = WN / 16;

    __shared__ float Ah[BM][BKP], Al[BM][BKP];
    __shared__ float Bh[BK][BNP], Bl[BK][BNP];

    const float* Bp = B + (long long)blockIdx.z * bStride;
    float* Cp = C + (long long)blockIdx.z * cStride;

    int tid = threadIdx.x;
    int rb = blockIdx.y * BM;
    int cb = blockIdx.x * BN;
    int warp = tid >> 5;
    int wr = warp & 3, wc = warp >> 2;

    wmma::fragment<wmma::accumulator, 16, 16, 8, float> acc[2][CF];
#pragma unroll
    for (int r = 0; r < 2; r++)
#pragma unroll
        for (int c = 0; c < CF; c++) wmma::fill_fragment(acc[r][c], 0.f);

    int ar = tid >> 1;            // 0..127
    int ac = (tid & 1) * 8;       // 0 or 8
    constexpr int BPT = (BK * BN) / 256;   // floats per thread for B (8 or 4)
    int br = (tid * BPT) / BN;
    int bc = (tid * BPT) % BN;

    for (int k0 = 0; k0 < K; k0 += BK) {
        float4 v0 = make_float4(0.f, 0.f, 0.f, 0.f), v1 = v0;
        if (rb + ar < M) {
            const float* ap = A + (size_t)(rb + ar) * K + k0 + ac;
            v0 = *reinterpret_cast<const float4*>(ap);
            v1 = *reinterpret_cast<const float4*>(ap + 4);
        }
        float va[8] = {v0.x, v0.y, v0.z, v0.w, v1.x, v1.y, v1.z, v1.w};
#pragma unroll
        for (int i = 0; i < 8; i++) {
            float hi = f2tf32(va[i]);
            Ah[ar][ac + i] = hi;
            Al[ar][ac + i] = f2tf32(va[i] - hi);
        }
        const float* bp = Bp + (size_t)(k0 + br) * N + cb + bc;
#pragma unroll
        for (int j = 0; j < BPT; j += 4) {
            float4 bv = *reinterpret_cast<const float4*>(bp + j);
            float vb[4] = {bv.x, bv.y, bv.z, bv.w};
#pragma unroll
            for (int i = 0; i < 4; i++) {
                float hi = f2tf32(vb[i]);
                Bh[br][bc + j + i] = hi;
                Bl[br][bc + j + i] = f2tf32(vb[i] - hi);
            }
        }
        __syncthreads();

#pragma unroll
        for (int ks = 0; ks < 2; ks++) {
            wmma::fragment<wmma::matrix_a, 16, 16, 8, wmma::precision::tf32, wmma::row_major> ah[2], alo[2];
#pragma unroll
            for (int r = 0; r < 2; r++) {
                wmma::load_matrix_sync(ah[r],  &Ah[wr * 32 + r * 16][ks * 8], BKP);
                wmma::load_matrix_sync(alo[r], &Al[wr * 32 + r * 16][ks * 8], BKP);
            }
            wmma::fragment<wmma::matrix_b, 16, 16, 8, wmma::precision::tf32, wmma::row_major> bh[CF], blo[CF];
#pragma unroll
            for (int c = 0; c < CF; c++) {
                wmma::load_matrix_sync(bh[c],  &Bh[ks * 8][wc * WN + c * 16], BNP);
                wmma::load_matrix_sync(blo[c], &Bl[ks * 8][wc * WN + c * 16], BNP);
            }
#pragma unroll
            for (int r = 0; r < 2; r++)
#pragma unroll
                for (int c = 0; c < CF; c++) {
                    wmma::mma_sync(acc[r][c], ah[r],  bh[c],  acc[r][c]);
                    wmma::mma_sync(acc[r][c], ah[r],  blo[c], acc[r][c]);
                    wmma::mma_sync(acc[r][c], alo[r], bh[c],  acc[r][c]);
                }
        }
        __syncthreads();
    }

#pragma unroll
    for (int r = 0; r < 2; r++)
#pragma unroll
        for (int c = 0; c < CF; c++) {
            int row = rb + wr * 32 + r * 16;
            int col = cb + wc * WN + c * 16;
            wmma::store_matrix_sync(Cp + (size_t)row * N + col, acc[r][c], N, wmma::mem_row_major);
        }
}

// ---------------- input FC bias add ----------------
__global__ void bias64_k(float* __restrict__ h, const float* __restrict__ b0,
                         const float* __restrict__ b1)
{
    int t = blockIdx.x * blockDim.x + threadIdx.x;
    if (t >= NTOT * 64) return;
    int n = t >> 6, d = t & 63;
    h[t] += (n < NTYPE0) ? b0[d] : b1[d];
}

// ---------------- pack layer-2 weights: [W2g0 | W2g1 | res2g0 | res2g1] ----------------
__global__ void pack_w2_k(const float* __restrict__ W2, const float* __restrict__ res2,
                          float* __restrict__ out)
{
    int idx = blockIdx.x * blockDim.x + threadIdx.x;
    if (idx >= 256 * 64) return;
    int k = idx >> 6, d = idx & 63;
    int g = (d >> 4) & 1;
    int which = d >> 5;
    int dd = d & 15;
    const float* src = which == 0 ? W2 : res2;
    out[idx] = src[(size_t)g * 256 * 16 + k * 16 + dd];
}

// ---------------- attention scores: warp per (node, head) ----------------
__global__ void scores_k(const float* __restrict__ feat, int stride,
                         const float* __restrict__ al, const float* __restrict__ ar,
                         float* __restrict__ el, float* __restrict__ er, int H, int D)
{
    int n = blockIdx.x;
    int wid = threadIdx.x >> 5;
    int lane = threadIdx.x & 31;
    const float* f = feat + (size_t)n * stride + wid * D;
    float sl = 0.f, sr = 0.f;
    for (int d = lane; d < D; d += 32) {
        float v = f[d];
        sl += v * al[wid * D + d];
        sr += v * ar[wid * D + d];
    }
#pragma unroll
    for (int o = 16; o > 0; o >>= 1) {
        sl += __shfl_down_sync(~0u, sl, o);
        sr += __shfl_down_sync(~0u, sr, o);
    }
    if (lane == 0) { el[n * H + wid] = sl; er[n * H + wid] = sr; }
}

// ---------------- edge softmax (CSR, warp per dst node) ----------------
template <int H>
__global__ void softmax_k(const int* __restrict__ rowptr, const int* __restrict__ csrsrc,
                          const float* __restrict__ el, const float* __restrict__ er,
                          float* __restrict__ alpha)
{
    int n = blockIdx.x * (blockDim.x >> 5) + (threadIdx.x >> 5);
    int lane = threadIdx.x & 31;
    if (n >= NTOT) return;
    int beg = rowptr[n], end = rowptr[n + 1];
    if (beg == end) return;

    float erh[H];
#pragma unroll
    for (int h = 0; h < H; h++) erh[h] = er[n * H + h];

    float mx[H];
#pragma unroll
    for (int h = 0; h < H; h++) mx[h] = -1e30f;

    for (int p = beg + lane; p < end; p += 32) {
        int s = csrsrc[p];
#pragma unroll
        for (int h = 0; h < H; h++) {
            float e = el[s * H + h] + erh[h];
            e = e > 0.f ? e : 0.2f * e;
            alpha[p * H + h] = e;
            mx[h] = fmaxf(mx[h], e);
        }
    }
#pragma unroll
    for (int h = 0; h < H; h++)
#pragma unroll
        for (int o = 16; o > 0; o >>= 1)
            mx[h] = fmaxf(mx[h], __shfl_xor_sync(~0u, mx[h], o));

    float den[H];
#pragma unroll
    for (int h = 0; h < H; h++) den[h] = 0.f;
    for (int p = beg + lane; p < end; p += 32) {
#pragma unroll
        for (int h = 0; h < H; h++) {
            float x = expf(alpha[p * H + h] - mx[h]);
            alpha[p * H + h] = x;
            den[h] += x;
        }
    }
#pragma unroll
    for (int h = 0; h < H; h++)
#pragma unroll
        for (int o = 16; o > 0; o >>= 1)
            den[h] += __shfl_xor_sync(~0u, den[h], o);

    float inv[H];
#pragma unroll
    for (int h = 0; h < H; h++) inv[h] = 1.f / den[h];
    for (int p = beg + lane; p < end; p += 32) {
#pragma unroll
        for (int h = 0; h < H; h++) alpha[p * H + h] *= inv[h];
    }
}

// ---------------- fused dual-graph aggregation + epilogue (HD=256) ----------------
__global__ void aggr256_k(const int* __restrict__ rp0, const int* __restrict__ cs0,
                          const float* __restrict__ a0, const float* __restrict__ f0,
                          const int* __restrict__ rp1, const int* __restrict__ cs1,
                          const float* __restrict__ a1, const float* __restrict__ f1,
                          const float* __restrict__ h, const float* __restrict__ bias0,
                          const float* __restrict__ bias1, const float* __restrict__ mixw,
                          int layer, int useRes, float* __restrict__ out)
{
    int n = blockIdx.x;
    int d = threadIdx.x;
    int head = d >> 6;

    float acc0 = 0.f, acc1 = 0.f;
    int b = rp0[n], e = rp0[n + 1];
    for (int p = b; p < e; p++) {
        int s = __ldg(&cs0[p]);
        float a = __ldg(&a0[p * 4 + head]);
        acc0 += f0[(size_t)s * 256 + d] * a;
    }
    b = rp1[n]; e = rp1[n + 1];
    for (int p = b; p < e; p++) {
        int s = __ldg(&cs1[p]);
        float a = __ldg(&a1[p * 4 + head]);
        acc1 += f1[(size_t)s * 256 + d] * a;
    }

    float res = useRes ? h[(size_t)n * 256 + d] : 0.f;
    float v0 = acc0 + res + bias0[d];
    float v1 = acc1 + res + bias1[d];
    v0 = v0 > 0.f ? v0 : expm1f(v0);
    v1 = v1 > 0.f ? v1 : expm1f(v1);

    int ty = (n < NTYPE0) ? 0 : 1;
    float m0 = mixw[ty * 6 + layer * 2 + 0];
    float m1 = mixw[ty * 6 + layer * 2 + 1];
    float mxw = fmaxf(m0, m1);
    float e0 = expf(m0 - mxw), e1 = expf(m1 - mxw);
    float inv = 1.f / (e0 + e1);
    out[(size_t)n * 256 + d] = v0 * (e0 * inv) + v1 * (e1 * inv);
}

// ---------------- layer 2 aggregation (H=1, D=16), packed l2 buffer ----------------
__global__ void aggr16_k(const int* __restrict__ rp0, const int* __restrict__ cs0,
                         const float* __restrict__ a0,
                         const int* __restrict__ rp1, const int* __restrict__ cs1,
                         const float* __restrict__ a1,
                         const float* __restrict__ l2, const float* __restrict__ b2,
                         const float* __restrict__ mixw, float* __restrict__ logits)
{
    int n = blockIdx.x * 16 + (threadIdx.x >> 4);
    int d = threadIdx.x & 15;
    if (n >= NTOT) return;

    float acc0 = 0.f, acc1 = 0.f;
    int b = rp0[n], e = rp0[n + 1];
    for (int p = b; p < e; p++)
        acc0 += l2[(size_t)__ldg(&cs0[p]) * 64 + d] * __ldg(&a0[p]);
    b = rp1[n]; e = rp1[n + 1];
    for (int p = b; p < e; p++)
        acc1 += l2[(size_t)__ldg(&cs1[p]) * 64 + 16 + d] * __ldg(&a1[p]);

    float v0 = acc0 + l2[(size_t)n * 64 + 32 + d] + b2[d];
    float v1 = acc1 + l2[(size_t)n * 64 + 48 + d] + b2[16 + d];

    int ty = (n < NTYPE0) ? 0 : 1;
    float m0 = mixw[ty * 6 + 4 + 0];
    float m1 = mixw[ty * 6 + 4 + 1];
    float mxw = fmaxf(m0, m1);
    float e0 = expf(m0 - mxw), e1 = expf(m1 - mxw);
    float inv = 1.f / (e0 + e1);
    logits[(size_t)n * 16 + d] = v0 * (e0 * inv) + v1 * (e1 * inv);
}

// ---------------- host orchestration ----------------
extern "C" void kernel_launch(void* const* d_in, const int* in_sizes, int n_in,
                              void* d_out, int out_size)
{
    const float* features0 = (const float*)d_in[0];
    const float* features1 = (const float*)d_in[1];
    const float* fc_w0 = (const float*)d_in[2];
    const float* fc_b0 = (const float*)d_in[3];
    const float* fc_w1 = (const float*)d_in[4];
    const float* fc_b1 = (const float*)d_in[5];
    const float* mix_w = (const float*)d_in[6];
    const float* W0  = (const float*)d_in[7];
    const float* al0 = (const float*)d_in[8];
    const float* ar0 = (const float*)d_in[9];
    const float* b0  = (const float*)d_in[10];
    const float* W1  = (const float*)d_in[11];
    const float* al1 = (const float*)d_in[12];
    const float* ar1 = (const float*)d_in[13];
    const float* b1  = (const float*)d_in[14];
    const float* W2  = (const float*)d_in[15];
    const float* al2 = (const float*)d_in[16];
    const float* ar2 = (const float*)d_in[17];
    const float* b2  = (const float*)d_in[18];
    const float* res2= (const float*)d_in[19];
    const int* srcs[2] = {(const int*)d_in[20], (const int*)d_in[22]};
    const int* dsts[2] = {(const int*)d_in[21], (const int*)d_in[23]};

    float *h, *acc, *featb, *l2out, *w2pack, *elp, *erp, *alphap;
    int *rowptrp, *cursorp, *countsp, *csrsrcp;
    cudaGetSymbolAddress((void**)&h,      g_h);
    cudaGetSymbolAddress((void**)&acc,    g_acc);
    cudaGetSymbolAddress((void**)&featb,  g_feat);
    cudaGetSymbolAddress((void**)&l2out,  g_l2out);
    cudaGetSymbolAddress((void**)&w2pack, g_w2pack);
    cudaGetSymbolAddress((void**)&elp,    g_el);
    cudaGetSymbolAddress((void**)&erp,    g_er);
    cudaGetSymbolAddress((void**)&alphap, g_alpha);
    cudaGetSymbolAddress((void**)&rowptrp, g_rowptr);
    cudaGetSymbolAddress((void**)&cursorp, g_cursor);
    cudaGetSymbolAddress((void**)&countsp, g_counts);
    cudaGetSymbolAddress((void**)&csrsrcp, g_csrsrc);

    float* feat[2]  = {featb, featb + (size_t)NPAD * 256};
    float* el[2]    = {elp, elp + NTOT * 4};
    float* er[2]    = {erp, erp + NTOT * 4};
    float* alpha[2] = {alphap, alphap + ETOT * 4};
    int* rowptr[2]  = {rowptrp, rowptrp + NTOT + 1};
    int* cursor[2]  = {cursorp, cursorp + NTOT};
    int* counts[2]  = {countsp, countsp + NTOT};
    int* csrsrc[2]  = {csrsrcp, csrsrcp + ETOT};

    const int TPB = 256;
    const int N1n = NTOT - NTYPE0;
    const int EB = (ETOT + TPB - 1) / TPB;
    const int MB = (NTOT + 127) / 128;      // 391

    // ---- build CSR for both graphs (reused by all 3 layers) ----
    for (int gi = 0; gi < 2; gi++) {
        cudaMemsetAsync(counts[gi], 0, NTOT * sizeof(int));
        count_k<<<EB, TPB>>>(dsts[gi], counts[gi]);
        scan_k<<<1, 1024>>>(counts[gi], rowptr[gi], cursor[gi]);
        scatter_k<<<EB, TPB>>>(srcs[gi], dsts[gi], cursor[gi], csrsrc[gi]);
    }
    pack_w2_k<<<64, 256>>>(W2, res2, w2pack);

    // ---- input per-type FC -> h (N, 64) ----
    gemm_tf32<64><<<dim3(1, (NTYPE0 + 127) / 128, 1), 256>>>(features0, fc_w0, h,
                                                             NTYPE0, 128, 64, 0, 0);
    gemm_tf32<64><<<dim3(1, (N1n + 127) / 128, 1), 256>>>(features1, fc_w1,
                                                          h + (size_t)NTYPE0 * 64,
                                                          N1n, 128, 64, 0, 0);
    bias64_k<<<(NTOT * 64 + TPB - 1) / TPB, TPB>>>(h, fc_b0, fc_b1);

    // ---- layers 0 and 1 (H=4, D=64, HD=256), both graphs fused via grid.z ----
    float* cur = h;
    float* nxt = acc;
    for (int l = 0; l < 2; l++) {
        int Kin = (l == 0) ? 64 : 256;
        const float* Wl  = (l == 0) ? W0 : W1;
        const float* all = (l == 0) ? al0 : al1;
        const float* arl = (l == 0) ? ar0 : ar1;
        const float* bl  = (l == 0) ? b0 : b1;
        gemm_tf32<128><<<dim3(2, MB, 2), 256>>>(cur, Wl, featb, NTOT, Kin, 256,
                                                (long long)Kin * 256, (long long)NPAD * 256);
        for (int gi = 0; gi < 2; gi++) {
            scores_k<<<NTOT, 128>>>(feat[gi], 256, all + gi * 256, arl + gi * 256,
                                    el[gi], er[gi], 4, 64);
            softmax_k<4><<<(NTOT + 7) / 8, 256>>>(rowptr[gi], csrsrc[gi], el[gi], er[gi], alpha[gi]);
        }
        aggr256_k<<<NTOT, 256>>>(rowptr[0], csrsrc[0], alpha[0], feat[0],
                                 rowptr[1], csrsrc[1], alpha[1], feat[1],
                                 cur, bl, bl + 256, mix_w, l, (l == 1) ? 1 : 0, nxt);
        float* t = cur; cur = nxt; nxt = t;
    }

    // ---- layer 2 (H=1, D=16): single packed N=64 GEMM, softmax, aggregate ----
    gemm_tf32<64><<<dim3(1, MB, 1), 256>>>(cur, w2pack, l2out, NTOT, 256, 64, 0, 0);
    for (int gi = 0; gi < 2; gi++) {
        scores_k<<<NTOT, 32>>>(l2out + gi * 16, 64, al2 + gi * 16, ar2 + gi * 16,
                               el[gi], er[gi], 1, 16);
        softmax_k<1><<<(NTOT + 7) / 8, 256>>>(rowptr[gi], csrsrc[gi], el[gi], er[gi], alpha[gi]);
    }
    aggr16_k<<<(NTOT + 15) / 16, 256>>>(rowptr[0], csrsrc[0], alpha[0],
                                        rowptr[1], csrsrc[1], alpha[1],
                                        l2out, b2, mix_w, (float*)d_out);
}

// round 4
// speedup vs baseline: 1.3590x; 1.3590x over previous
#include <cuda_runtime.h>
#include <math.h>

#define NTOT   50000
#define NTYPE0 30000
#define ETOT   400000
#define NPAD   50048

// ---------------- static scratch ----------------
__device__ float g_h[NPAD * 256];
__device__ float g_acc[NPAD * 256];
__device__ float g_feat[2 * NPAD * 256];
__device__ float g_l2out[NPAD * 64];
__device__ float g_w2pack[256 * 64];
__device__ float g_el[2][NTOT * 4];
__device__ float g_er[2][NTOT * 4];
__device__ float g_alpha[2][ETOT * 4];
__device__ int   g_rowptr[2][NTOT + 1];
__device__ int   g_cursor[2][NTOT];
__device__ int   g_counts[2][NTOT];
__device__ int   g_csrsrc[2][ETOT];

// ---------------- packed f32x2 helpers (FFMA2: 2x fp32 FMA rate on sm_103a) --------
__device__ __forceinline__ unsigned long long pack2(float x, float y) {
    unsigned long long r;
    asm("mov.b64 %0, {%1, %2};" : "=l"(r) : "f"(x), "f"(y));
    return r;
}
__device__ __forceinline__ void ffma2(unsigned long long& d, unsigned long long a,
                                      unsigned long long b) {
    asm("fma.rn.f32x2 %0, %1, %2, %3;" : "=l"(d) : "l"(a), "l"(b), "l"(d));
}
__device__ __forceinline__ float2 unpack2(unsigned long long v) {
    float2 r;
    asm("mov.b64 {%0, %1}, %2;" : "=f"(r.x), "=f"(r.y) : "l"(v));
    return r;
}

// ---------------- CSR build ----------------
__global__ void count_k(const int* __restrict__ dst, int* __restrict__ counts)
{
    int e = blockIdx.x * blockDim.x + threadIdx.x;
    if (e < ETOT) atomicAdd(&counts[dst[e]], 1);
}

__global__ void scan_k(const int* __restrict__ counts, int* __restrict__ rowptr,
                       int* __restrict__ cursor)
{
    __shared__ int warp_sums[32];
    __shared__ int s_carry;
    int tid = threadIdx.x, lane = tid & 31, wid = tid >> 5;
    int nw = blockDim.x >> 5;
    if (tid == 0) s_carry = 0;
    __syncthreads();
    for (int base = 0; base < NTOT; base += blockDim.x) {
        int i = base + tid;
        int v = (i < NTOT) ? counts[i] : 0;
        int x = v;
#pragma unroll
        for (int o = 1; o < 32; o <<= 1) {
            int y = __shfl_up_sync(~0u, x, o);
            if (lane >= o) x += y;
        }
        if (lane == 31) warp_sums[wid] = x;
        __syncthreads();
        if (wid == 0) {
            int s = (lane < nw) ? warp_sums[lane] : 0;
#pragma unroll
            for (int o = 1; o < 32; o <<= 1) {
                int y = __shfl_up_sync(~0u, s, o);
                if (lane >= o) s += y;
            }
            warp_sums[lane] = s;
        }
        __syncthreads();
        int woff = (wid == 0) ? 0 : warp_sums[wid - 1];
        int incl = x + woff;
        int excl = incl - v;
        int carry = s_carry;
        if (i < NTOT) { rowptr[i] = carry + excl; cursor[i] = carry + excl; }
        __syncthreads();
        if (tid == blockDim.x - 1) s_carry = carry + incl;
        __syncthreads();
    }
    if (tid == 0) rowptr[NTOT] = s_carry;
}

__global__ void scatter_k(const int* __restrict__ src, const int* __restrict__ dst,
                          int* __restrict__ cursor, int* __restrict__ csrsrc)
{
    int e = blockIdx.x * blockDim.x + threadIdx.x;
    if (e >= ETOT) return;
    int pos = atomicAdd(&cursor[dst[e]], 1);
    csrsrc[pos] = src[e];
}

// ---------------- 64x64 tile fp32 GEMM with FFMA2 (small-N cases) ----------------
__global__ void gemm64(const float* __restrict__ A, const float* __restrict__ B,
                       const float* __restrict__ bias, float* __restrict__ C,
                       int M, int K, int N)
{
    __shared__ float As[16][65];
    __shared__ float Bs[16][64];
    int tid = threadIdx.x;
    int rowBase = blockIdx.y * 64;
    int colBase = blockIdx.x * 64;
    int tx = tid & 15, ty = tid >> 4;
    int arow = tid >> 2, acol = (tid & 3) << 2;
    int brow = tid >> 4, bcol = (tid & 15) << 2;

    unsigned long long acc[4][2];
#pragma unroll
    for (int i = 0; i < 4; i++) { acc[i][0] = 0ull; acc[i][1] = 0ull; }

    for (int k0 = 0; k0 < K; k0 += 16) {
        float4 av = make_float4(0.f, 0.f, 0.f, 0.f);
        if (rowBase + arow < M)
            av = *reinterpret_cast<const float4*>(A + (size_t)(rowBase + arow) * K + k0 + acol);
        As[acol + 0][arow] = av.x; As[acol + 1][arow] = av.y;
        As[acol + 2][arow] = av.z; As[acol + 3][arow] = av.w;
        float4 bv = make_float4(0.f, 0.f, 0.f, 0.f);
        if (colBase + bcol < N)
            bv = *reinterpret_cast<const float4*>(B + (size_t)(k0 + brow) * N + colBase + bcol);
        *reinterpret_cast<float4*>(&Bs[brow][bcol]) = bv;
        __syncthreads();
#pragma unroll
        for (int k = 0; k < 16; k++) {
            float a0 = As[k][(ty << 2) + 0], a1 = As[k][(ty << 2) + 1];
            float a2 = As[k][(ty << 2) + 2], a3 = As[k][(ty << 2) + 3];
            unsigned long long b01 = *reinterpret_cast<const unsigned long long*>(&Bs[k][(tx << 2) + 0]);
            unsigned long long b23 = *reinterpret_cast<const unsigned long long*>(&Bs[k][(tx << 2) + 2]);
            unsigned long long p0 = pack2(a0, a0), p1 = pack2(a1, a1);
            unsigned long long p2 = pack2(a2, a2), p3 = pack2(a3, a3);
            ffma2(acc[0][0], p0, b01); ffma2(acc[0][1], p0, b23);
            ffma2(acc[1][0], p1, b01); ffma2(acc[1][1], p1, b23);
            ffma2(acc[2][0], p2, b01); ffma2(acc[2][1], p2, b23);
            ffma2(acc[3][0], p3, b01); ffma2(acc[3][1], p3, b23);
        }
        __syncthreads();
    }
#pragma unroll
    for (int i = 0; i < 4; i++) {
        int r = rowBase + (ty << 2) + i;
        if (r >= M) continue;
        float2 u0 = unpack2(acc[i][0]);
        float2 u1 = unpack2(acc[i][1]);
        float vals[4] = {u0.x, u0.y, u1.x, u1.y};
#pragma unroll
        for (int j = 0; j < 4; j++) {
            int c = colBase + (tx << 2) + j;
            if (c < N) C[(size_t)r * N + c] = vals[j] + (bias ? bias[c] : 0.f);
        }
    }
}

// ---------------- 128x128 tile fp32 GEMM with FFMA2 ----------------
// 256 threads, 8x8 microtile. Requires N % 128 == 0, K % 8 == 0.
// grid.z selects B/C slab (dual-graph fusion).
__global__ void __launch_bounds__(256, 2)
gemm128(const float* __restrict__ A, const float* __restrict__ B,
        float* __restrict__ C, int M, int K, int N,
        long long bStride, long long cStride)
{
    __shared__ float As[8][132];
    __shared__ float Bs[8][128];
    const float* Bp = B + (long long)blockIdx.z * bStride;
    float* Cp = C + (long long)blockIdx.z * cStride;

    int tid = threadIdx.x;
    int rb = blockIdx.y * 128, cb = blockIdx.x * 128;
    int tx = tid & 15, ty = tid >> 4;
    int arow = tid >> 1, acol = (tid & 1) << 2;
    int brow = tid >> 5, bcol = (tid & 31) << 2;

    unsigned long long acc[8][4];
#pragma unroll
    for (int i = 0; i < 8; i++)
#pragma unroll
        for (int j = 0; j < 4; j++) acc[i][j] = 0ull;

    for (int k0 = 0; k0 < K; k0 += 8) {
        float4 av = make_float4(0.f, 0.f, 0.f, 0.f);
        if (rb + arow < M)
            av = *reinterpret_cast<const float4*>(A + (size_t)(rb + arow) * K + k0 + acol);
        As[acol + 0][arow] = av.x; As[acol + 1][arow] = av.y;
        As[acol + 2][arow] = av.z; As[acol + 3][arow] = av.w;
        float4 bv = *reinterpret_cast<const float4*>(Bp + (size_t)(k0 + brow) * N + cb + bcol);
        *reinterpret_cast<float4*>(&Bs[brow][bcol]) = bv;
        __syncthreads();
#pragma unroll
        for (int k = 0; k < 8; k++) {
            float a[8];
            *reinterpret_cast<float4*>(a)     = *reinterpret_cast<float4*>(&As[k][ty * 8]);
            *reinterpret_cast<float4*>(a + 4) = *reinterpret_cast<float4*>(&As[k][ty * 8 + 4]);
            unsigned long long b2[4];
            b2[0] = *reinterpret_cast<const unsigned long long*>(&Bs[k][tx * 4]);
            b2[1] = *reinterpret_cast<const unsigned long long*>(&Bs[k][tx * 4 + 2]);
            b2[2] = *reinterpret_cast<const unsigned long long*>(&Bs[k][64 + tx * 4]);
            b2[3] = *reinterpret_cast<const unsigned long long*>(&Bs[k][64 + tx * 4 + 2]);
#pragma unroll
            for (int i = 0; i < 8; i++) {
                unsigned long long aa = pack2(a[i], a[i]);
                ffma2(acc[i][0], aa, b2[0]);
                ffma2(acc[i][1], aa, b2[1]);
                ffma2(acc[i][2], aa, b2[2]);
                ffma2(acc[i][3], aa, b2[3]);
            }
        }
        __syncthreads();
    }
#pragma unroll
    for (int i = 0; i < 8; i++) {
        int r = rb + ty * 8 + i;
        if (r >= M) continue;
        float2 u0 = unpack2(acc[i][0]), u1 = unpack2(acc[i][1]);
        float2 u2 = unpack2(acc[i][2]), u3 = unpack2(acc[i][3]);
        float4 v0 = make_float4(u0.x, u0.y, u1.x, u1.y);
        float4 v1 = make_float4(u2.x, u2.y, u3.x, u3.y);
        *reinterpret_cast<float4*>(Cp + (size_t)r * N + cb + tx * 4) = v0;
        *reinterpret_cast<float4*>(Cp + (size_t)r * N + cb + 64 + tx * 4) = v1;
    }
}

// ---------------- pack layer-2 weights: cols = [W2g0 | W2g1 | res2g0 | res2g1] ------
__global__ void pack_w2_k(const float* __restrict__ W2, const float* __restrict__ res2,
                          float* __restrict__ out)
{
    int idx = blockIdx.x * blockDim.x + threadIdx.x;
    if (idx >= 256 * 64) return;
    int k = idx >> 6, d = idx & 63;
    int g = (d >> 4) & 1;
    int which = d >> 5;
    int dd = d & 15;
    const float* src = which == 0 ? W2 : res2;
    out[idx] = src[(size_t)g * 256 * 16 + k * 16 + dd];
}

// ---------------- attention scores: warp per (node, head) ----------------
__global__ void scores_k(const float* __restrict__ feat, int stride,
                         const float* __restrict__ al, const float* __restrict__ ar,
                         float* __restrict__ el, float* __restrict__ er, int H, int D)
{
    int n = blockIdx.x;
    int wid = threadIdx.x >> 5;
    int lane = threadIdx.x & 31;
    const float* f = feat + (size_t)n * stride + wid * D;
    float sl = 0.f, sr = 0.f;
    for (int d = lane; d < D; d += 32) {
        float v = f[d];
        sl += v * al[wid * D + d];
        sr += v * ar[wid * D + d];
    }
#pragma unroll
    for (int o = 16; o > 0; o >>= 1) {
        sl += __shfl_down_sync(~0u, sl, o);
        sr += __shfl_down_sync(~0u, sr, o);
    }
    if (lane == 0) { el[n * H + wid] = sl; er[n * H + wid] = sr; }
}

// ---------------- edge softmax (CSR, warp per dst node) ----------------
template <int H>
__global__ void softmax_k(const int* __restrict__ rowptr, const int* __restrict__ csrsrc,
                          const float* __restrict__ el, const float* __restrict__ er,
                          float* __restrict__ alpha)
{
    int n = blockIdx.x * (blockDim.x >> 5) + (threadIdx.x >> 5);
    int lane = threadIdx.x & 31;
    if (n >= NTOT) return;
    int beg = rowptr[n], end = rowptr[n + 1];
    if (beg == end) return;

    float erh[H];
#pragma unroll
    for (int h = 0; h < H; h++) erh[h] = er[n * H + h];

    float mx[H];
#pragma unroll
    for (int h = 0; h < H; h++) mx[h] = -1e30f;

    for (int p = beg + lane; p < end; p += 32) {
        int s = csrsrc[p];
#pragma unroll
        for (int h = 0; h < H; h++) {
            float e = el[s * H + h] + erh[h];
            e = e > 0.f ? e : 0.2f * e;
            alpha[p * H + h] = e;
            mx[h] = fmaxf(mx[h], e);
        }
    }
#pragma unroll
    for (int h = 0; h < H; h++)
#pragma unroll
        for (int o = 16; o > 0; o >>= 1)
            mx[h] = fmaxf(mx[h], __shfl_xor_sync(~0u, mx[h], o));

    float den[H];
#pragma unroll
    for (int h = 0; h < H; h++) den[h] = 0.f;
    for (int p = beg + lane; p < end; p += 32) {
#pragma unroll
        for (int h = 0; h < H; h++) {
            float x = expf(alpha[p * H + h] - mx[h]);
            alpha[p * H + h] = x;
            den[h] += x;
        }
    }
#pragma unroll
    for (int h = 0; h < H; h++)
#pragma unroll
        for (int o = 16; o > 0; o >>= 1)
            den[h] += __shfl_xor_sync(~0u, den[h], o);

    float inv[H];
#pragma unroll
    for (int h = 0; h < H; h++) inv[h] = 1.f / den[h];
    for (int p = beg + lane; p < end; p += 32) {
#pragma unroll
        for (int h = 0; h < H; h++) alpha[p * H + h] *= inv[h];
    }
}

// ---------------- fused dual-graph aggregation + epilogue (HD=256) ----------------
__global__ void aggr256_k(const int* __restrict__ rp0, const int* __restrict__ cs0,
                          const float* __restrict__ a0, const float* __restrict__ f0,
                          const int* __restrict__ rp1, const int* __restrict__ cs1,
                          const float* __restrict__ a1, const float* __restrict__ f1,
                          const float* __restrict__ h, const float* __restrict__ bias0,
                          const float* __restrict__ bias1, const float* __restrict__ mixw,
                          int layer, int useRes, float* __restrict__ out)
{
    int n = blockIdx.x;
    int d = threadIdx.x;
    int head = d >> 6;

    float acc0 = 0.f, acc1 = 0.f;
    int b = rp0[n], e = rp0[n + 1];
    for (int p = b; p < e; p++) {
        int s = __ldg(&cs0[p]);
        float a = __ldg(&a0[p * 4 + head]);
        acc0 += f0[(size_t)s * 256 + d] * a;
    }
    b = rp1[n]; e = rp1[n + 1];
    for (int p = b; p < e; p++) {
        int s = __ldg(&cs1[p]);
        float a = __ldg(&a1[p * 4 + head]);
        acc1 += f1[(size_t)s * 256 + d] * a;
    }

    float res = useRes ? h[(size_t)n * 256 + d] : 0.f;
    float v0 = acc0 + res + bias0[d];
    float v1 = acc1 + res + bias1[d];
    v0 = v0 > 0.f ? v0 : expm1f(v0);
    v1 = v1 > 0.f ? v1 : expm1f(v1);

    int ty = (n < NTYPE0) ? 0 : 1;
    float m0 = mixw[ty * 6 + layer * 2 + 0];
    float m1 = mixw[ty * 6 + layer * 2 + 1];
    float mxw = fmaxf(m0, m1);
    float e0 = expf(m0 - mxw), e1 = expf(m1 - mxw);
    float inv = 1.f / (e0 + e1);
    out[(size_t)n * 256 + d] = v0 * (e0 * inv) + v1 * (e1 * inv);
}

// ---------------- layer 2 aggregation (H=1, D=16), packed l2 buffer ----------------
__global__ void aggr16_k(const int* __restrict__ rp0, const int* __restrict__ cs0,
                         const float* __restrict__ a0,
                         const int* __restrict__ rp1, const int* __restrict__ cs1,
                         const float* __restrict__ a1,
                         const float* __restrict__ l2, const float* __restrict__ b2,
                         const float* __restrict__ mixw, float* __restrict__ logits)
{
    int n = blockIdx.x * 16 + (threadIdx.x >> 4);
    int d = threadIdx.x & 15;
    if (n >= NTOT) return;

    float acc0 = 0.f, acc1 = 0.f;
    int b = rp0[n], e = rp0[n + 1];
    for (int p = b; p < e; p++)
        acc0 += l2[(size_t)__ldg(&cs0[p]) * 64 + d] * __ldg(&a0[p]);
    b = rp1[n]; e = rp1[n + 1];
    for (int p = b; p < e; p++)
        acc1 += l2[(size_t)__ldg(&cs1[p]) * 64 + 16 + d] * __ldg(&a1[p]);

    float v0 = acc0 + l2[(size_t)n * 64 + 32 + d] + b2[d];
    float v1 = acc1 + l2[(size_t)n * 64 + 48 + d] + b2[16 + d];

    int ty = (n < NTYPE0) ? 0 : 1;
    float m0 = mixw[ty * 6 + 4 + 0];
    float m1 = mixw[ty * 6 + 4 + 1];
    float mxw = fmaxf(m0, m1);
    float e0 = expf(m0 - mxw), e1 = expf(m1 - mxw);
    float inv = 1.f / (e0 + e1);
    logits[(size_t)n * 16 + d] = v0 * (e0 * inv) + v1 * (e1 * inv);
}

// ---------------- host orchestration ----------------
extern "C" void kernel_launch(void* const* d_in, const int* in_sizes, int n_in,
                              void* d_out, int out_size)
{
    const float* features0 = (const float*)d_in[0];
    const float* features1 = (const float*)d_in[1];
    const float* fc_w0 = (const float*)d_in[2];
    const float* fc_b0 = (const float*)d_in[3];
    const float* fc_w1 = (const float*)d_in[4];
    const float* fc_b1 = (const float*)d_in[5];
    const float* mix_w = (const float*)d_in[6];
    const float* W0  = (const float*)d_in[7];
    const float* al0 = (const float*)d_in[8];
    const float* ar0 = (const float*)d_in[9];
    const float* b0  = (const float*)d_in[10];
    const float* W1  = (const float*)d_in[11];
    const float* al1 = (const float*)d_in[12];
    const float* ar1 = (const float*)d_in[13];
    const float* b1  = (const float*)d_in[14];
    const float* W2  = (const float*)d_in[15];
    const float* al2 = (const float*)d_in[16];
    const float* ar2 = (const float*)d_in[17];
    const float* b2  = (const float*)d_in[18];
    const float* res2= (const float*)d_in[19];
    const int* srcs[2] = {(const int*)d_in[20], (const int*)d_in[22]};
    const int* dsts[2] = {(const int*)d_in[21], (const int*)d_in[23]};

    float *h, *acc, *featb, *l2out, *w2pack, *elp, *erp, *alphap;
    int *rowptrp, *cursorp, *countsp, *csrsrcp;
    cudaGetSymbolAddress((void**)&h,      g_h);
    cudaGetSymbolAddress((void**)&acc,    g_acc);
    cudaGetSymbolAddress((void**)&featb,  g_feat);
    cudaGetSymbolAddress((void**)&l2out,  g_l2out);
    cudaGetSymbolAddress((void**)&w2pack, g_w2pack);
    cudaGetSymbolAddress((void**)&elp,    g_el);
    cudaGetSymbolAddress((void**)&erp,    g_er);
    cudaGetSymbolAddress((void**)&alphap, g_alpha);
    cudaGetSymbolAddress((void**)&rowptrp, g_rowptr);
    cudaGetSymbolAddress((void**)&cursorp, g_cursor);
    cudaGetSymbolAddress((void**)&countsp, g_counts);
    cudaGetSymbolAddress((void**)&csrsrcp, g_csrsrc);

    float* feat[2]  = {featb, featb + (size_t)NPAD * 256};
    float* el[2]    = {elp, elp + NTOT * 4};
    float* er[2]    = {erp, erp + NTOT * 4};
    float* alpha[2] = {alphap, alphap + ETOT * 4};
    int* rowptr[2]  = {rowptrp, rowptrp + NTOT + 1};
    int* cursor[2]  = {cursorp, cursorp + NTOT};
    int* counts[2]  = {countsp, countsp + NTOT};
    int* csrsrc[2]  = {csrsrcp, csrsrcp + ETOT};

    const int TPB = 256;
    const int N1n = NTOT - NTYPE0;
    const int EB = (ETOT + TPB - 1) / TPB;
    const int MB = (NTOT + 127) / 128;

    // ---- build CSR for both graphs (reused by all 3 layers) ----
    for (int gi = 0; gi < 2; gi++) {
        cudaMemsetAsync(counts[gi], 0, NTOT * sizeof(int));
        count_k<<<EB, TPB>>>(dsts[gi], counts[gi]);
        scan_k<<<1, 1024>>>(counts[gi], rowptr[gi], cursor[gi]);
        scatter_k<<<EB, TPB>>>(srcs[gi], dsts[gi], cursor[gi], csrsrc[gi]);
    }
    pack_w2_k<<<64, 256>>>(W2, res2, w2pack);

    // ---- input per-type FC -> h (N, 64) ----
    gemm64<<<dim3(1, (NTYPE0 + 63) / 64), TPB>>>(features0, fc_w0, fc_b0, h, NTYPE0, 128, 64);
    gemm64<<<dim3(1, (N1n + 63) / 64), TPB>>>(features1, fc_w1, fc_b1,
                                              h + (size_t)NTYPE0 * 64, N1n, 128, 64);

    // ---- layers 0 and 1 (H=4, D=64, HD=256), both graphs via grid.z ----
    float* cur = h;
    float* nxt = acc;
    for (int l = 0; l < 2; l++) {
        int Kin = (l == 0) ? 64 : 256;
        const float* Wl  = (l == 0) ? W0 : W1;
        const float* all = (l == 0) ? al0 : al1;
        const float* arl = (l == 0) ? ar0 : ar1;
        const float* bl  = (l == 0) ? b0 : b1;
        gemm128<<<dim3(2, MB, 2), 256>>>(cur, Wl, featb, NTOT, Kin, 256,
                                         (long long)Kin * 256, (long long)NPAD * 256);
        for (int gi = 0; gi < 2; gi++) {
            scores_k<<<NTOT, 128>>>(feat[gi], 256, all + gi * 256, arl + gi * 256,
                                    el[gi], er[gi], 4, 64);
            softmax_k<4><<<(NTOT + 7) / 8, 256>>>(rowptr[gi], csrsrc[gi], el[gi], er[gi], alpha[gi]);
        }
        aggr256_k<<<NTOT, 256>>>(rowptr[0], csrsrc[0], alpha[0], feat[0],
                                 rowptr[1], csrsrc[1], alpha[1], feat[1],
                                 cur, bl, bl + 256, mix_w, l, (l == 1) ? 1 : 0, nxt);
        float* t = cur; cur = nxt; nxt = t;
    }

    // ---- layer 2 (H=1, D=16): single packed N=64 GEMM, softmax, aggregate ----
    gemm64<<<dim3(1, (NTOT + 63) / 64), TPB>>>(cur, w2pack, nullptr, l2out, NTOT, 256, 64);
    for (int gi = 0; gi < 2; gi++) {
        scores_k<<<NTOT, 32>>>(l2out + gi * 16, 64, al2 + gi * 16, ar2 + gi * 16,
                               el[gi], er[gi], 1, 16);
        softmax_k<1><<<(NTOT + 7) / 8, 256>>>(rowptr[gi], csrsrc[gi], el[gi], er[gi], alpha[gi]);
    }
    aggr16_k<<<(NTOT + 15) / 16, 256>>>(rowptr[0], csrsrc[0], alpha[0],
                                        rowptr[1], csrsrc[1], alpha[1],
                                        l2out, b2, mix_w, (float*)d_out);
}